// round 10
// baseline (speedup 1.0000x reference)
#include <cuda_runtime.h>
#include <cuda_fp16.h>
#include <cstdint>

#define N_NODES 100000
#define N_EDGES 1600000
#define FEAT 64

#define SCAN_TPB 1024
#define SCAN_PER_THREAD 4
#define SCAN_CHUNK (SCAN_TPB * SCAN_PER_THREAD)                      // 4096
#define SCAN_NBLOCKS ((N_NODES + SCAN_CHUNK - 1) / SCAN_CHUNK)       // 25
#define FLAG_VALID (1 << 30)
#define FLAG_MASK  (FLAG_VALID - 1)

// ---------------- scratch (static device globals: allocation-free) ----------
__device__ __half g_H[N_NODES * FEAT];  // transformed features, fp16 STORAGE
__device__ float  g_A[N_NODES * FEAT];  // activations stay fp32
__device__ float  g_dinv[N_NODES];
__device__ int    g_rowstart[N_NODES + 1];
__device__ int    g_cursor[N_NODES];
// csr as int4 array for 16B-aligned uniform loads; pairs of {src, norm-bits}.
// +8 edge pad (zero-initialized, never written) so aligned groups can overrun.
__device__ int4   g_csr4[(N_EDGES + 8) / 2];
__device__ int    g_zr[N_NODES + 64];   // deg + lookback flags, one memset

// ---------------- GEMM (fp32 compute, fp16 H output) -------------------------

__device__ __forceinline__ void gemm_body(const float* __restrict__ X,
                                          const float* __restrict__ W,
                                          int row0, int tid,
                                          float (*Xs)[64], float (*Ws)[64]) {
    {
        const float4* W4 = (const float4*)W;
        float4* Ws4 = (float4*)Ws;
        #pragma unroll
        for (int i = 0; i < 4; i++) Ws4[tid + 256 * i] = W4[tid + 256 * i];
    }
    {
        float4* Xs4 = (float4*)Xs;
        const float4* X4 = (const float4*)X;
        #pragma unroll
        for (int i = 0; i < 4; i++) {
            int li = tid + 256 * i;
            int grow = row0 + (li >> 4);
            Xs4[li] = (grow < N_NODES) ? X4[(size_t)grow * 16 + (li & 15)]
                                       : make_float4(0.f, 0.f, 0.f, 0.f);
        }
    }
    __syncthreads();

    int tc = tid & 15;
    int tr = tid >> 4;

    float acc[4][4];
    #pragma unroll
    for (int i = 0; i < 4; i++)
        #pragma unroll
        for (int j = 0; j < 4; j++) acc[i][j] = 0.f;

    #pragma unroll 8
    for (int k = 0; k < 64; k++) {
        float4 bq = *(const float4*)&Ws[k][4 * tc];
        float a0 = Xs[4 * tr + 0][k];
        float a1 = Xs[4 * tr + 1][k];
        float a2 = Xs[4 * tr + 2][k];
        float a3 = Xs[4 * tr + 3][k];
        acc[0][0] = fmaf(a0, bq.x, acc[0][0]);
        acc[0][1] = fmaf(a0, bq.y, acc[0][1]);
        acc[0][2] = fmaf(a0, bq.z, acc[0][2]);
        acc[0][3] = fmaf(a0, bq.w, acc[0][3]);
        acc[1][0] = fmaf(a1, bq.x, acc[1][0]);
        acc[1][1] = fmaf(a1, bq.y, acc[1][1]);
        acc[1][2] = fmaf(a1, bq.z, acc[1][2]);
        acc[1][3] = fmaf(a1, bq.w, acc[1][3]);
        acc[2][0] = fmaf(a2, bq.x, acc[2][0]);
        acc[2][1] = fmaf(a2, bq.y, acc[2][1]);
        acc[2][2] = fmaf(a2, bq.z, acc[2][2]);
        acc[2][3] = fmaf(a2, bq.w, acc[2][3]);
        acc[3][0] = fmaf(a3, bq.x, acc[3][0]);
        acc[3][1] = fmaf(a3, bq.y, acc[3][1]);
        acc[3][2] = fmaf(a3, bq.z, acc[3][2]);
        acc[3][3] = fmaf(a3, bq.w, acc[3][3]);
    }

    #pragma unroll
    for (int i = 0; i < 4; i++) {
        int grow = row0 + 4 * tr + i;
        if (grow < N_NODES) {
            __half2 h0 = __floats2half2_rn(acc[i][0], acc[i][1]);
            __half2 h1 = __floats2half2_rn(acc[i][2], acc[i][3]);
            uint2 pk = make_uint2(*(const unsigned*)&h0, *(const unsigned*)&h1);
            ((uint2*)(g_H + (size_t)grow * FEAT))[tc] = pk;
        }
    }
}

// Fused: gemm1 + degree histogram (independent work).
__global__ __launch_bounds__(256) void gemm1_hist_kernel(const float* __restrict__ X,
                                                         const float* __restrict__ W,
                                                         const int* __restrict__ dst,
                                                         int gemmBlocks) {
    __shared__ float Xs[64][64];
    __shared__ float Ws[64][64];
    int bid = blockIdx.x;
    if (bid < gemmBlocks) {
        gemm_body(X, W, bid * 64, threadIdx.x, Xs, Ws);
    } else {
        int e4 = (bid - gemmBlocks) * blockDim.x + threadIdx.x;
        if (e4 < N_EDGES / 4) {
            int4 d = ((const int4*)dst)[e4];
            atomicAdd(&g_zr[d.x], 1);
            atomicAdd(&g_zr[d.y], 1);
            atomicAdd(&g_zr[d.z], 1);
            atomicAdd(&g_zr[d.w], 1);
        }
    }
}

__global__ __launch_bounds__(256) void gemm_kernel(const float* __restrict__ X,
                                                   const float* __restrict__ W) {
    __shared__ float Xs[64][64];
    __shared__ float Ws[64][64];
    gemm_body(X, W, blockIdx.x * 64, threadIdx.x, Xs, Ws);
}

// ---------------- graph preprocessing ---------------------------------------

__global__ void scan_kernel() {
    __shared__ int warp_sums[32];
    __shared__ int prefix_s;
    int tid = threadIdx.x;
    int lane = tid & 31, wid = tid >> 5;
    int b = blockIdx.x;
    int idx0 = b * SCAN_CHUNK + tid * SCAN_PER_THREAD;

    int v[SCAN_PER_THREAD];
    int sum = 0;
    #pragma unroll
    for (int j = 0; j < SCAN_PER_THREAD; j++) {
        int i = idx0 + j;
        v[j] = (i < N_NODES) ? g_zr[i] : 0;
        sum += v[j];
    }
    int x = sum;
    #pragma unroll
    for (int d = 1; d < 32; d <<= 1) {
        int t = __shfl_up_sync(0xFFFFFFFFu, x, d);
        if (lane >= d) x += t;
    }
    if (lane == 31) warp_sums[wid] = x;
    __syncthreads();
    if (wid == 0) {
        int s = warp_sums[lane];
        #pragma unroll
        for (int d = 1; d < 32; d <<= 1) {
            int t = __shfl_up_sync(0xFFFFFFFFu, s, d);
            if (lane >= d) s += t;
        }
        warp_sums[lane] = s;
    }
    __syncthreads();
    int thread_excl = (x - sum) + (wid ? warp_sums[wid - 1] : 0);
    int block_total = warp_sums[31];

    if (tid == 0) {
        int pre = 0;
        if (b > 0) {
            int f;
            do { f = atomicAdd(&g_zr[N_NODES + b - 1], 0); } while (f == 0);
            pre = f & FLAG_MASK;
        }
        __threadfence();
        atomicExch(&g_zr[N_NODES + b], FLAG_VALID | (pre + block_total));
        prefix_s = pre;
        if (b == SCAN_NBLOCKS - 1) g_rowstart[N_NODES] = pre + block_total;
    }
    __syncthreads();
    int run = prefix_s + thread_excl;

    #pragma unroll
    for (int j = 0; j < SCAN_PER_THREAD; j++) {
        int i = idx0 + j;
        if (i < N_NODES) {
            g_rowstart[i] = run;
            g_cursor[i]   = run;
            g_dinv[i] = rsqrtf((float)v[j] + 1.0f);
        }
        run += v[j];
    }
}

__global__ void csr_build_kernel(const int* __restrict__ src,
                                 const int* __restrict__ dst) {
    int e4 = blockIdx.x * blockDim.x + threadIdx.x;
    int2* csr = (int2*)g_csr4;
    if (e4 < N_EDGES / 4) {
        int4 s = __ldg(&((const int4*)src)[e4]);
        int4 d = __ldg(&((const int4*)dst)[e4]);
        {
            int pos = atomicAdd(&g_cursor[d.x], 1);
            csr[pos] = make_int2(s.x, __float_as_int(g_dinv[s.x] * g_dinv[d.x]));
        }
        {
            int pos = atomicAdd(&g_cursor[d.y], 1);
            csr[pos] = make_int2(s.y, __float_as_int(g_dinv[s.y] * g_dinv[d.y]));
        }
        {
            int pos = atomicAdd(&g_cursor[d.z], 1);
            csr[pos] = make_int2(s.z, __float_as_int(g_dinv[s.z] * g_dinv[d.z]));
        }
        {
            int pos = atomicAdd(&g_cursor[d.w], 1);
            csr[pos] = make_int2(s.w, __float_as_int(g_dinv[s.w] * g_dinv[d.w]));
        }
    }
}

// ---------------- aggregation --------------------------------------------------
// Warp per dst row. NO shuffles: all lanes issue the SAME csr address (HW
// broadcast, L1-resident line reused 16x). 8-edge aligned groups via 4 uniform
// int4 loads; out-of-range slots get nm=0 (u is still a valid node id).
// 8 independent half2 gathers in flight per group; fp32 accumulate.
__global__ __launch_bounds__(256, 4) void agg_kernel(const float* __restrict__ b,
                                                     float* __restrict__ out,
                                                     int relu) {
    int lane = threadIdx.x & 31, wid = threadIdx.x >> 5;
    int row = blockIdx.x * 8 + wid;
    if (row >= N_NODES) return;

    int s = g_rowstart[row];
    int e = g_rowstart[row + 1];

    float2 acc = make_float2(0.f, 0.f);
    const __half2* H2 = (const __half2*)g_H;

    for (int base = (s & ~7); base < e; base += 8) {
        int4 q0 = __ldg(&g_csr4[(base >> 1) + 0]);
        int4 q1 = __ldg(&g_csr4[(base >> 1) + 1]);
        int4 q2 = __ldg(&g_csr4[(base >> 1) + 2]);
        int4 q3 = __ldg(&g_csr4[(base >> 1) + 3]);
        int   u[8];
        float nm[8];
        u[0] = q0.x; nm[0] = __int_as_float(q0.y);
        u[1] = q0.z; nm[1] = __int_as_float(q0.w);
        u[2] = q1.x; nm[2] = __int_as_float(q1.y);
        u[3] = q1.z; nm[3] = __int_as_float(q1.w);
        u[4] = q2.x; nm[4] = __int_as_float(q2.y);
        u[5] = q2.z; nm[5] = __int_as_float(q2.w);
        u[6] = q3.x; nm[6] = __int_as_float(q3.y);
        u[7] = q3.z; nm[7] = __int_as_float(q3.w);
        #pragma unroll
        for (int j = 0; j < 8; j++) {
            int idx = base + j;
            if (idx < s || idx >= e) nm[j] = 0.f;       // pad slots contribute 0
            u[j] &= 0x1FFFF;                            // keep gather in-bounds (<=131071)
        }
        __half2 v[8];
        #pragma unroll
        for (int j = 0; j < 8; j++)
            v[j] = H2[(size_t)u[j] * 32 + lane];
        #pragma unroll
        for (int j = 0; j < 8; j++) {
            float2 vf = __half22float2(v[j]);
            acc.x = fmaf(nm[j], vf.x, acc.x);
            acc.y = fmaf(nm[j], vf.y, acc.y);
        }
    }

    float di = g_dinv[row];
    float sw = di * di;
    float2 vf = __half22float2(H2[(size_t)row * 32 + lane]);
    float2 bv = ((const float2*)b)[lane];
    acc.x = fmaf(sw, vf.x, acc.x) + bv.x;
    acc.y = fmaf(sw, vf.y, acc.y) + bv.y;
    if (relu) {
        acc.x = fmaxf(acc.x, 0.f);
        acc.y = fmaxf(acc.y, 0.f);
    }
    ((float2*)(out + (size_t)row * FEAT))[lane] = acc;
}

// ---------------- launch ------------------------------------------------------

extern "C" void kernel_launch(void* const* d_in, const int* in_sizes, int n_in,
                              void* d_out, int out_size) {
    const float* x   = (const float*)d_in[0];
    const int*   ei  = (const int*)d_in[1];
    const float* W1  = (const float*)d_in[2];
    const float* b1  = (const float*)d_in[3];
    const float* W2  = (const float*)d_in[4];
    const float* b2  = (const float*)d_in[5];
    const float* W3  = (const float*)d_in[6];
    const float* b3  = (const float*)d_in[7];
    float* out = (float*)d_out;

    const int* src = ei;
    const int* dst = ei + N_EDGES;

    const int TB = 256;
    const int edge4Blocks = (N_EDGES / 4 + TB - 1) / TB;   // 1563
    const int warpBlocks  = (N_NODES + 7) / 8;             // 12500
    const int gemmBlocks  = (N_NODES + 63) / 64;           // 1563

    void* zr_ptr = nullptr;
    cudaGetSymbolAddress(&zr_ptr, g_zr);
    cudaMemsetAsync(zr_ptr, 0, sizeof(int) * (N_NODES + 64));

    gemm1_hist_kernel<<<gemmBlocks + edge4Blocks, TB>>>(x, W1, dst, gemmBlocks);
    scan_kernel<<<SCAN_NBLOCKS, SCAN_TPB>>>();
    csr_build_kernel<<<edge4Blocks, TB>>>(src, dst);

    agg_kernel<<<warpBlocks, TB>>>(b1, g_A, 1);

    gemm_kernel<<<gemmBlocks, TB>>>(g_A, W2);
    agg_kernel<<<warpBlocks, TB>>>(b2, g_A, 1);

    gemm_kernel<<<gemmBlocks, TB>>>(g_A, W3);
    agg_kernel<<<warpBlocks, TB>>>(b3, out, 0);

    (void)in_sizes; (void)n_in; (void)out_size;
}

// round 11
// speedup vs baseline: 2.3418x; 2.3418x over previous
#include <cuda_runtime.h>
#include <cuda_fp16.h>
#include <cstdint>

#define N_NODES 100000
#define N_EDGES 1600000
#define FEAT 64
#define TPB 256
#define NBLK 592                              // 148 SMs x 4 blocks, all co-resident
#define NTILE ((N_NODES + 63) / 64)           // 1563 gemm tiles
#define NE4 (N_EDGES / 4)                     // 400000
#define NRG ((N_NODES + 7) / 8)               // 12500 row groups

#define SCAN_PT 16
#define SCAN_CHUNK (TPB * SCAN_PT)            // 4096
#define SCAN_NBLOCKS ((N_NODES + SCAN_CHUNK - 1) / SCAN_CHUNK)   // 25
#define FLAG_VALID (1 << 30)
#define FLAG_MASK  (FLAG_VALID - 1)

// ---------------- scratch (static device globals: allocation-free) ----------
__device__ __half g_H[N_NODES * FEAT];        // transformed features (fp16 storage)
__device__ float  g_A[N_NODES * FEAT];        // activations (fp32)
__device__ float  g_dinv[N_NODES];
__device__ int    g_rowstart[N_NODES + 1];
__device__ int    g_cursor[N_NODES];
__device__ int2   g_csr[N_EDGES];             // {src, norm-as-int-bits}
__device__ int    g_zr[N_NODES + 64];         // deg + lookback flags (one memset)
__device__ unsigned g_barTicket = 0;          // monotone grid-barrier ticket (never reset)

// ---- grid-wide barrier: monotone ticket, replay-safe, all blocks resident ----
__device__ __forceinline__ void grid_barrier() {
    __syncthreads();
    if (threadIdx.x == 0) {
        __threadfence();
        unsigned old = atomicAdd(&g_barTicket, 1u);
        unsigned target = (old / NBLK + 1u) * NBLK;
        while (atomicAdd(&g_barTicket, 0u) < target) __nanosleep(64);
        __threadfence();
    }
    __syncthreads();
}

// ---------------- gemm phase: H = X @ W (fp32 compute, fp16 out) --------------
__device__ __forceinline__ void gemm_phase(const float* __restrict__ X,
                                           const float* __restrict__ W,
                                           int tid, int bid,
                                           float (*Xs)[64], float (*Ws)[64]) {
    // W loaded ONCE per phase (same for all tiles)
    {
        const float4* W4 = (const float4*)W;
        float4* Ws4 = (float4*)Ws;
        #pragma unroll
        for (int i = 0; i < 4; i++) Ws4[tid + 256 * i] = W4[tid + 256 * i];
    }
    __syncthreads();
    int tc = tid & 15;
    int tr = tid >> 4;

    for (int t = bid; t < NTILE; t += NBLK) {
        int row0 = t * 64;
        {
            float4* Xs4 = (float4*)Xs;
            const float4* X4 = (const float4*)X;
            #pragma unroll
            for (int i = 0; i < 4; i++) {
                int li = tid + 256 * i;
                int grow = row0 + (li >> 4);
                Xs4[li] = (grow < N_NODES) ? X4[(size_t)grow * 16 + (li & 15)]
                                           : make_float4(0.f, 0.f, 0.f, 0.f);
            }
        }
        __syncthreads();

        float acc[4][4];
        #pragma unroll
        for (int i = 0; i < 4; i++)
            #pragma unroll
            for (int j = 0; j < 4; j++) acc[i][j] = 0.f;

        #pragma unroll 8
        for (int k = 0; k < 64; k++) {
            float4 bq = *(const float4*)&Ws[k][4 * tc];
            float a0 = Xs[4 * tr + 0][k];
            float a1 = Xs[4 * tr + 1][k];
            float a2 = Xs[4 * tr + 2][k];
            float a3 = Xs[4 * tr + 3][k];
            acc[0][0] = fmaf(a0, bq.x, acc[0][0]);
            acc[0][1] = fmaf(a0, bq.y, acc[0][1]);
            acc[0][2] = fmaf(a0, bq.z, acc[0][2]);
            acc[0][3] = fmaf(a0, bq.w, acc[0][3]);
            acc[1][0] = fmaf(a1, bq.x, acc[1][0]);
            acc[1][1] = fmaf(a1, bq.y, acc[1][1]);
            acc[1][2] = fmaf(a1, bq.z, acc[1][2]);
            acc[1][3] = fmaf(a1, bq.w, acc[1][3]);
            acc[2][0] = fmaf(a2, bq.x, acc[2][0]);
            acc[2][1] = fmaf(a2, bq.y, acc[2][1]);
            acc[2][2] = fmaf(a2, bq.z, acc[2][2]);
            acc[2][3] = fmaf(a2, bq.w, acc[2][3]);
            acc[3][0] = fmaf(a3, bq.x, acc[3][0]);
            acc[3][1] = fmaf(a3, bq.y, acc[3][1]);
            acc[3][2] = fmaf(a3, bq.z, acc[3][2]);
            acc[3][3] = fmaf(a3, bq.w, acc[3][3]);
        }

        #pragma unroll
        for (int i = 0; i < 4; i++) {
            int grow = row0 + 4 * tr + i;
            if (grow < N_NODES) {
                __half2 h0 = __floats2half2_rn(acc[i][0], acc[i][1]);
                __half2 h1 = __floats2half2_rn(acc[i][2], acc[i][3]);
                uint2 pk = make_uint2(*(const unsigned*)&h0, *(const unsigned*)&h1);
                ((uint2*)(g_H + (size_t)grow * FEAT))[tc] = pk;
            }
        }
        __syncthreads();   // protect Xs before next tile overwrites
    }
}

// ---------------- agg phase (best R9 body, persistent row loop) ----------------
__device__ __forceinline__ void agg_phase(const float* __restrict__ b,
                                          float* __restrict__ out, int relu,
                                          int lane, int wid, int bid) {
    const __half2* H2 = (const __half2*)g_H;
    for (int rg = bid; rg < NRG; rg += NBLK) {
        int row = rg * 8 + wid;
        if (row >= N_NODES) continue;

        int s = g_rowstart[row];
        int e = g_rowstart[row + 1];
        float2 acc = make_float2(0.f, 0.f);

        for (int base = s; base < e; base += 32) {
            int idx = base + lane;
            int2 p = (idx < e) ? __ldg(&g_csr[idx]) : make_int2(row, 0);
            int cnt = e - base;
            if (cnt > 32) cnt = 32;
            for (int g0 = 0; g0 < cnt; g0 += 8) {
                int   u[8];
                float nm[8];
                #pragma unroll
                for (int j = 0; j < 8; j++) {
                    u[j]  = __shfl_sync(0xFFFFFFFFu, p.x, g0 + j);
                    nm[j] = __int_as_float(__shfl_sync(0xFFFFFFFFu, p.y, g0 + j));
                }
                __half2 v[8];
                #pragma unroll
                for (int j = 0; j < 8; j++)
                    v[j] = H2[(size_t)u[j] * 32 + lane];
                #pragma unroll
                for (int j = 0; j < 8; j++) {
                    float2 vf = __half22float2(v[j]);
                    acc.x = fmaf(nm[j], vf.x, acc.x);
                    acc.y = fmaf(nm[j], vf.y, acc.y);
                }
            }
        }

        float di = g_dinv[row];
        float sw = di * di;
        float2 vf = __half22float2(H2[(size_t)row * 32 + lane]);
        float2 bv = ((const float2*)b)[lane];
        acc.x = fmaf(sw, vf.x, acc.x) + bv.x;
        acc.y = fmaf(sw, vf.y, acc.y) + bv.y;
        if (relu) {
            acc.x = fmaxf(acc.x, 0.f);
            acc.y = fmaxf(acc.y, 0.f);
        }
        ((float2*)(out + (size_t)row * FEAT))[lane] = acc;
    }
}

// ---------------- the megakernel ----------------------------------------------
__global__ __launch_bounds__(TPB, 4) void mega_kernel(
    const float* __restrict__ x,
    const int*   __restrict__ src,
    const int*   __restrict__ dst,
    const float* __restrict__ W1, const float* __restrict__ b1,
    const float* __restrict__ W2, const float* __restrict__ b2,
    const float* __restrict__ W3, const float* __restrict__ b3,
    float* __restrict__ out)
{
    __shared__ float Xs[64][64];
    __shared__ float Ws[64][64];
    __shared__ int   s_wsum[8];
    __shared__ int   s_prefix;

    int tid = threadIdx.x;
    int bid = blockIdx.x;
    int lane = tid & 31, wid = tid >> 5;

    // ---- phase 0: degree histogram + gemm1 (independent) ----
    for (int e4 = bid * TPB + tid; e4 < NE4; e4 += NBLK * TPB) {
        int4 d = __ldg(&((const int4*)dst)[e4]);
        atomicAdd(&g_zr[d.x], 1);
        atomicAdd(&g_zr[d.y], 1);
        atomicAdd(&g_zr[d.z], 1);
        atomicAdd(&g_zr[d.w], 1);
    }
    gemm_phase(x, W1, tid, bid, Xs, Ws);
    grid_barrier();

    // ---- phase 1: lookback scan (blocks 0..24) ----
    if (bid < SCAN_NBLOCKS) {
        int idx0 = bid * SCAN_CHUNK + tid * SCAN_PT;
        int v[SCAN_PT];
        int sum = 0;
        #pragma unroll
        for (int j = 0; j < SCAN_PT; j++) {
            int i = idx0 + j;
            v[j] = (i < N_NODES) ? g_zr[i] : 0;
            sum += v[j];
        }
        int xsc = sum;
        #pragma unroll
        for (int d2 = 1; d2 < 32; d2 <<= 1) {
            int t2 = __shfl_up_sync(0xFFFFFFFFu, xsc, d2);
            if (lane >= d2) xsc += t2;
        }
        if (lane == 31) s_wsum[wid] = xsc;
        __syncthreads();
        if (wid == 0) {
            int sv = (lane < 8) ? s_wsum[lane] : 0;
            #pragma unroll
            for (int d2 = 1; d2 < 8; d2 <<= 1) {
                int t2 = __shfl_up_sync(0xFFFFFFFFu, sv, d2);
                if (lane >= d2) sv += t2;
            }
            if (lane < 8) s_wsum[lane] = sv;
        }
        __syncthreads();
        int thr_excl = (xsc - sum) + (wid ? s_wsum[wid - 1] : 0);
        int blk_total = s_wsum[7];

        if (tid == 0) {
            int pre = 0;
            if (bid > 0) {
                int f;
                do { f = atomicAdd(&g_zr[N_NODES + bid - 1], 0); } while (f == 0);
                pre = f & FLAG_MASK;
            }
            __threadfence();
            atomicExch(&g_zr[N_NODES + bid], FLAG_VALID | (pre + blk_total));
            s_prefix = pre;
            if (bid == SCAN_NBLOCKS - 1) g_rowstart[N_NODES] = pre + blk_total;
        }
        __syncthreads();
        int run = s_prefix + thr_excl;
        #pragma unroll
        for (int j = 0; j < SCAN_PT; j++) {
            int i = idx0 + j;
            if (i < N_NODES) {
                g_rowstart[i] = run;
                g_cursor[i]   = run;
                g_dinv[i] = rsqrtf((float)v[j] + 1.0f);
            }
            run += v[j];
        }
    }
    grid_barrier();

    // ---- phase 2: csr build ----
    for (int e4 = bid * TPB + tid; e4 < NE4; e4 += NBLK * TPB) {
        int4 s4 = __ldg(&((const int4*)src)[e4]);
        int4 d4 = __ldg(&((const int4*)dst)[e4]);
        {
            int pos = atomicAdd(&g_cursor[d4.x], 1);
            g_csr[pos] = make_int2(s4.x, __float_as_int(g_dinv[s4.x] * g_dinv[d4.x]));
        }
        {
            int pos = atomicAdd(&g_cursor[d4.y], 1);
            g_csr[pos] = make_int2(s4.y, __float_as_int(g_dinv[s4.y] * g_dinv[d4.y]));
        }
        {
            int pos = atomicAdd(&g_cursor[d4.z], 1);
            g_csr[pos] = make_int2(s4.z, __float_as_int(g_dinv[s4.z] * g_dinv[d4.z]));
        }
        {
            int pos = atomicAdd(&g_cursor[d4.w], 1);
            g_csr[pos] = make_int2(s4.w, __float_as_int(g_dinv[s4.w] * g_dinv[d4.w]));
        }
    }
    grid_barrier();

    // ---- layers ----
    agg_phase(b1, g_A, 1, lane, wid, bid);
    grid_barrier();
    gemm_phase(g_A, W2, tid, bid, Xs, Ws);
    grid_barrier();
    agg_phase(b2, g_A, 1, lane, wid, bid);
    grid_barrier();
    gemm_phase(g_A, W3, tid, bid, Xs, Ws);
    grid_barrier();
    agg_phase(b3, out, 0, lane, wid, bid);
}

// ---------------- launch ------------------------------------------------------

extern "C" void kernel_launch(void* const* d_in, const int* in_sizes, int n_in,
                              void* d_out, int out_size) {
    const float* x   = (const float*)d_in[0];
    const int*   ei  = (const int*)d_in[1];
    const float* W1  = (const float*)d_in[2];
    const float* b1  = (const float*)d_in[3];
    const float* W2  = (const float*)d_in[4];
    const float* b2  = (const float*)d_in[5];
    const float* W3  = (const float*)d_in[6];
    const float* b3  = (const float*)d_in[7];
    float* out = (float*)d_out;

    const int* src = ei;
    const int* dst = ei + N_EDGES;

    void* zr_ptr = nullptr;
    cudaGetSymbolAddress(&zr_ptr, g_zr);
    cudaMemsetAsync(zr_ptr, 0, sizeof(int) * (N_NODES + 64));

    mega_kernel<<<NBLK, TPB>>>(x, src, dst, W1, b1, W2, b2, W3, b3, out);

    (void)in_sizes; (void)n_in; (void)out_size;
}

// round 12
// speedup vs baseline: 2.6440x; 1.1290x over previous
#include <cuda_runtime.h>
#include <cuda_fp16.h>
#include <cstdint>

#define N_NODES 100000
#define N_EDGES 1600000
#define FEAT 64
#define TPB 256
#define NBLK 592                              // 148 SMs x 4 blocks, all co-resident
#define NTILE ((N_NODES + 63) / 64)           // 1563 gemm tiles
#define NE4 (N_EDGES / 4)                     // 400000
#define NRG ((N_NODES + 7) / 8)               // 12500 row groups

#define SCAN_PT 16
#define SCAN_CHUNK (TPB * SCAN_PT)            // 4096
#define SCAN_NBLOCKS ((N_NODES + SCAN_CHUNK - 1) / SCAN_CHUNK)   // 25
#define FLAG_VALID (1 << 30)
#define FLAG_MASK  (FLAG_VALID - 1)

// ---------------- scratch (static device globals: allocation-free) ----------
// H' = dinv * (X@W), fp16, with ONE extra zero pad row at index N_NODES.
__device__ __half g_H[(N_NODES + 1) * FEAT];
__device__ float  g_A[N_NODES * FEAT];        // activations (fp32)
__device__ float  g_dinv[N_NODES];
__device__ int    g_rowstart[N_NODES + 1];
__device__ int    g_cursor[N_NODES];
__device__ int    g_csrsrc[N_EDGES];          // src-only CSR (norm folded into H')
__device__ int    g_zr[N_NODES + 64];         // deg + lookback flags (one memset)
__device__ unsigned g_barTicket = 0;          // monotone grid barrier (replay-safe)

// ---- grid-wide barrier: monotone ticket, all blocks resident ----
__device__ __forceinline__ void grid_barrier() {
    __syncthreads();
    if (threadIdx.x == 0) {
        __threadfence();
        unsigned old = atomicAdd(&g_barTicket, 1u);
        unsigned target = (old / NBLK + 1u) * NBLK;
        while (atomicAdd(&g_barTicket, 0u) < target) __nanosleep(64);
        __threadfence();
    }
    __syncthreads();
}

// ---------------- gemm phase: H' = dinv .* (X @ W), fp16 out ------------------
__device__ __forceinline__ void gemm_phase(const float* __restrict__ X,
                                           const float* __restrict__ W,
                                           int tid, int bid,
                                           float (*Xs)[64], float (*Ws)[64]) {
    {
        const float4* W4 = (const float4*)W;
        float4* Ws4 = (float4*)Ws;
        #pragma unroll
        for (int i = 0; i < 4; i++) Ws4[tid + 256 * i] = W4[tid + 256 * i];
    }
    __syncthreads();
    int tc = tid & 15;
    int tr = tid >> 4;

    for (int t = bid; t < NTILE; t += NBLK) {
        int row0 = t * 64;
        {
            float4* Xs4 = (float4*)Xs;
            const float4* X4 = (const float4*)X;
            #pragma unroll
            for (int i = 0; i < 4; i++) {
                int li = tid + 256 * i;
                int grow = row0 + (li >> 4);
                Xs4[li] = (grow < N_NODES) ? X4[(size_t)grow * 16 + (li & 15)]
                                           : make_float4(0.f, 0.f, 0.f, 0.f);
            }
        }
        __syncthreads();

        float acc[4][4];
        #pragma unroll
        for (int i = 0; i < 4; i++)
            #pragma unroll
            for (int j = 0; j < 4; j++) acc[i][j] = 0.f;

        #pragma unroll 8
        for (int k = 0; k < 64; k++) {
            float4 bq = *(const float4*)&Ws[k][4 * tc];
            float a0 = Xs[4 * tr + 0][k];
            float a1 = Xs[4 * tr + 1][k];
            float a2 = Xs[4 * tr + 2][k];
            float a3 = Xs[4 * tr + 3][k];
            acc[0][0] = fmaf(a0, bq.x, acc[0][0]);
            acc[0][1] = fmaf(a0, bq.y, acc[0][1]);
            acc[0][2] = fmaf(a0, bq.z, acc[0][2]);
            acc[0][3] = fmaf(a0, bq.w, acc[0][3]);
            acc[1][0] = fmaf(a1, bq.x, acc[1][0]);
            acc[1][1] = fmaf(a1, bq.y, acc[1][1]);
            acc[1][2] = fmaf(a1, bq.z, acc[1][2]);
            acc[1][3] = fmaf(a1, bq.w, acc[1][3]);
            acc[2][0] = fmaf(a2, bq.x, acc[2][0]);
            acc[2][1] = fmaf(a2, bq.y, acc[2][1]);
            acc[2][2] = fmaf(a2, bq.z, acc[2][2]);
            acc[2][3] = fmaf(a2, bq.w, acc[2][3]);
            acc[3][0] = fmaf(a3, bq.x, acc[3][0]);
            acc[3][1] = fmaf(a3, bq.y, acc[3][1]);
            acc[3][2] = fmaf(a3, bq.z, acc[3][2]);
            acc[3][3] = fmaf(a3, bq.w, acc[3][3]);
        }

        #pragma unroll
        for (int i = 0; i < 4; i++) {
            int grow = row0 + 4 * tr + i;
            if (grow < N_NODES) {
                float dv = g_dinv[grow];
                __half2 h0 = __floats2half2_rn(acc[i][0] * dv, acc[i][1] * dv);
                __half2 h1 = __floats2half2_rn(acc[i][2] * dv, acc[i][3] * dv);
                uint2 pk = make_uint2(*(const unsigned*)&h0, *(const unsigned*)&h1);
                ((uint2*)(g_H + (size_t)grow * FEAT))[tc] = pk;
            }
        }
        __syncthreads();
    }
}

// ---------------- agg phase: out = dinv[i]*(sum H'[u] + H'[i]) + b ------------
__device__ __forceinline__ void agg_phase(const float* __restrict__ b,
                                          float* __restrict__ out, int relu,
                                          int lane, int wid, int bid) {
    const __half2* H2 = (const __half2*)g_H;
    for (int rg = bid; rg < NRG; rg += NBLK) {
        int row = rg * 8 + wid;
        if (row >= N_NODES) continue;

        int s = g_rowstart[row];
        int e = g_rowstart[row + 1];
        float2 acc = make_float2(0.f, 0.f);

        for (int base = s; base < e; base += 32) {
            int idx = base + lane;
            // invalid lanes broadcast the zero pad row -> adds 0, no predication
            int uu = (idx < e) ? __ldg(&g_csrsrc[idx]) : N_NODES;
            int cnt = e - base;
            if (cnt > 32) cnt = 32;
            for (int g0 = 0; g0 < cnt; g0 += 8) {
                int u[8];
                #pragma unroll
                for (int j = 0; j < 8; j++)
                    u[j] = __shfl_sync(0xFFFFFFFFu, uu, g0 + j);
                __half2 v[8];
                #pragma unroll
                for (int j = 0; j < 8; j++)
                    v[j] = H2[(size_t)u[j] * 32 + lane];
                #pragma unroll
                for (int j = 0; j < 8; j++) {
                    float2 vf = __half22float2(v[j]);
                    acc.x += vf.x;
                    acc.y += vf.y;
                }
            }
        }

        float dv = g_dinv[row];
        float2 hr = __half22float2(H2[(size_t)row * 32 + lane]);
        float2 bv = ((const float2*)b)[lane];
        acc.x = fmaf(acc.x + hr.x, dv, bv.x);
        acc.y = fmaf(acc.y + hr.y, dv, bv.y);
        if (relu) {
            acc.x = fmaxf(acc.x, 0.f);
            acc.y = fmaxf(acc.y, 0.f);
        }
        ((float2*)(out + (size_t)row * FEAT))[lane] = acc;
    }
}

// ---------------- the megakernel ----------------------------------------------
__global__ __launch_bounds__(TPB, 4) void mega_kernel(
    const float* __restrict__ x,
    const int*   __restrict__ src,
    const int*   __restrict__ dst,
    const float* __restrict__ W1, const float* __restrict__ b1,
    const float* __restrict__ W2, const float* __restrict__ b2,
    const float* __restrict__ W3, const float* __restrict__ b3,
    float* __restrict__ out)
{
    __shared__ float Xs[64][64];
    __shared__ float Ws[64][64];
    __shared__ int   s_wsum[8];
    __shared__ int   s_prefix;

    int tid = threadIdx.x;
    int bid = blockIdx.x;
    int lane = tid & 31, wid = tid >> 5;

    // ---- phase 0: degree histogram; zero the H' pad row ----
    if (bid == 0 && tid < 16)
        ((uint2*)(g_H + (size_t)N_NODES * FEAT))[tid] = make_uint2(0u, 0u);
    for (int e4 = bid * TPB + tid; e4 < NE4; e4 += NBLK * TPB) {
        int4 d = __ldg(&((const int4*)dst)[e4]);
        atomicAdd(&g_zr[d.x], 1);
        atomicAdd(&g_zr[d.y], 1);
        atomicAdd(&g_zr[d.z], 1);
        atomicAdd(&g_zr[d.w], 1);
    }
    grid_barrier();

    // ---- phase 1: lookback scan -> rowstart, cursor, dinv ----
    if (bid < SCAN_NBLOCKS) {
        int idx0 = bid * SCAN_CHUNK + tid * SCAN_PT;
        int v[SCAN_PT];
        int sum = 0;
        #pragma unroll
        for (int j = 0; j < SCAN_PT; j++) {
            int i = idx0 + j;
            v[j] = (i < N_NODES) ? g_zr[i] : 0;
            sum += v[j];
        }
        int xsc = sum;
        #pragma unroll
        for (int d2 = 1; d2 < 32; d2 <<= 1) {
            int t2 = __shfl_up_sync(0xFFFFFFFFu, xsc, d2);
            if (lane >= d2) xsc += t2;
        }
        if (lane == 31) s_wsum[wid] = xsc;
        __syncthreads();
        if (wid == 0) {
            int sv = (lane < 8) ? s_wsum[lane] : 0;
            #pragma unroll
            for (int d2 = 1; d2 < 8; d2 <<= 1) {
                int t2 = __shfl_up_sync(0xFFFFFFFFu, sv, d2);
                if (lane >= d2) sv += t2;
            }
            if (lane < 8) s_wsum[lane] = sv;
        }
        __syncthreads();
        int thr_excl = (xsc - sum) + (wid ? s_wsum[wid - 1] : 0);
        int blk_total = s_wsum[7];

        if (tid == 0) {
            int pre = 0;
            if (bid > 0) {
                int f;
                do { f = atomicAdd(&g_zr[N_NODES + bid - 1], 0); } while (f == 0);
                pre = f & FLAG_MASK;
            }
            __threadfence();
            atomicExch(&g_zr[N_NODES + bid], FLAG_VALID | (pre + blk_total));
            s_prefix = pre;
            if (bid == SCAN_NBLOCKS - 1) g_rowstart[N_NODES] = pre + blk_total;
        }
        __syncthreads();
        int run = s_prefix + thr_excl;
        #pragma unroll
        for (int j = 0; j < SCAN_PT; j++) {
            int i = idx0 + j;
            if (i < N_NODES) {
                g_rowstart[i] = run;
                g_cursor[i]   = run;
                g_dinv[i] = rsqrtf((float)v[j] + 1.0f);
            }
            run += v[j];
        }
    }
    grid_barrier();

    // ---- phase 2: csr build (src only) + gemm1 (needs dinv; independent) ----
    for (int e4 = bid * TPB + tid; e4 < NE4; e4 += NBLK * TPB) {
        int4 s4 = __ldg(&((const int4*)src)[e4]);
        int4 d4 = __ldg(&((const int4*)dst)[e4]);
        g_csrsrc[atomicAdd(&g_cursor[d4.x], 1)] = s4.x;
        g_csrsrc[atomicAdd(&g_cursor[d4.y], 1)] = s4.y;
        g_csrsrc[atomicAdd(&g_cursor[d4.z], 1)] = s4.z;
        g_csrsrc[atomicAdd(&g_cursor[d4.w], 1)] = s4.w;
    }
    gemm_phase(x, W1, tid, bid, Xs, Ws);
    grid_barrier();

    // ---- layers ----
    agg_phase(b1, g_A, 1, lane, wid, bid);
    grid_barrier();
    gemm_phase(g_A, W2, tid, bid, Xs, Ws);
    grid_barrier();
    agg_phase(b2, g_A, 1, lane, wid, bid);
    grid_barrier();
    gemm_phase(g_A, W3, tid, bid, Xs, Ws);
    grid_barrier();
    agg_phase(b3, out, 0, lane, wid, bid);
}

// ---------------- launch ------------------------------------------------------

extern "C" void kernel_launch(void* const* d_in, const int* in_sizes, int n_in,
                              void* d_out, int out_size) {
    const float* x   = (const float*)d_in[0];
    const int*   ei  = (const int*)d_in[1];
    const float* W1  = (const float*)d_in[2];
    const float* b1  = (const float*)d_in[3];
    const float* W2  = (const float*)d_in[4];
    const float* b2  = (const float*)d_in[5];
    const float* W3  = (const float*)d_in[6];
    const float* b3  = (const float*)d_in[7];
    float* out = (float*)d_out;

    const int* src = ei;
    const int* dst = ei + N_EDGES;

    void* zr_ptr = nullptr;
    cudaGetSymbolAddress(&zr_ptr, g_zr);
    cudaMemsetAsync(zr_ptr, 0, sizeof(int) * (N_NODES + 64));

    mega_kernel<<<NBLK, TPB>>>(x, src, dst, W1, b1, W2, b2, W3, b3, out);

    (void)in_sizes; (void)n_in; (void)out_size;
}

// round 13
// speedup vs baseline: 3.0658x; 1.1595x over previous
#include <cuda_runtime.h>
#include <cuda_fp16.h>
#include <cstdint>

#define N_NODES 100000
#define N_EDGES 1600000
#define FEAT 64
#define TPB 256
#define NBLK 592                              // 148 SMs x 4 blocks, co-resident
#define NTILE ((N_NODES + 63) / 64)           // 1563 gemm tiles
#define NE4 (N_EDGES / 4)                     // 400000
#define NRG ((N_NODES + 7) / 8)               // 12500 row groups

#define SCAN_PT 16
#define SCAN_CHUNK (TPB * SCAN_PT)            // 4096
#define SCAN_NBLOCKS ((N_NODES + SCAN_CHUNK - 1) / SCAN_CHUNK)   // 25
#define FLAG_VALID (1 << 30)
#define FLAG_MASK  (FLAG_VALID - 1)

// ---------------- scratch (static device globals: allocation-free) ----------
// H' = dinv * (X@W), fp16, ONE zero pad row at index N_NODES.
__device__ __half g_H[(N_NODES + 1) * FEAT];
__device__ __half g_Ah[N_NODES * FEAT];       // activations, fp16 storage
__device__ float  g_dinv[N_NODES];
__device__ int    g_rowstart[N_NODES + 1];
__device__ int    g_cursor[N_NODES];
__device__ int    g_csrsrc[N_EDGES];          // src-only CSR (norm folded into H')
__device__ int    g_zr[N_NODES + 64];         // deg + lookback flags (one memset)
__device__ unsigned g_barTicket = 0;          // monotone grid barrier (replay-safe)

__device__ __forceinline__ uint32_t smem_u32(const void* p) {
    return (uint32_t)__cvta_generic_to_shared(p);
}

// ---- grid-wide barrier ----
__device__ __forceinline__ void grid_barrier() {
    __syncthreads();
    if (threadIdx.x == 0) {
        __threadfence();
        unsigned old = atomicAdd(&g_barTicket, 1u);
        unsigned target = (old / NBLK + 1u) * NBLK;
        while (atomicAdd(&g_barTicket, 0u) < target) __nanosleep(64);
        __threadfence();
    }
    __syncthreads();
}

// ---------------- tensor-core gemm: H' = dinv .* (X @ W) ----------------------
// 64x64 tile / block; 8 warps; warp = 16 rows x 32 cols via mma.m16n8k16.
// XKIND 0: X is fp32 global (layer 1). XKIND 1: X is fp16 global (g_Ah).
template<int XKIND>
__device__ __forceinline__ void gemm_phase_mma(const void* Xv,
                                               const float* __restrict__ W,
                                               int tid, int bid,
                                               __half (*Xs)[72], __half (*Wh)[72]) {
    // convert W (4096 fp32) to fp16 smem, once per phase
    {
        const float4* W4 = (const float4*)W;
        #pragma unroll
        for (int i = 0; i < 4; i++) {
            int li = tid + 256 * i;           // 1024 float4 groups
            int r = li >> 4, c4 = (li & 15) * 4;
            float4 w = W4[li];
            *(__half2*)&Wh[r][c4]     = __floats2half2_rn(w.x, w.y);
            *(__half2*)&Wh[r][c4 + 2] = __floats2half2_rn(w.z, w.w);
        }
    }
    int lane = tid & 31, w8 = tid >> 5;
    int rt = w8 & 3;            // row tile 0..3 (16 rows each)
    int ch = w8 >> 2;           // col half 0..1 (32 cols each)

    for (int t = bid; t < NTILE; t += NBLK) {
        int row0 = t * 64;
        // stage X tile (fp16)
        #pragma unroll
        for (int i = 0; i < 4; i++) {
            int li = tid + 256 * i;
            int r = li >> 4, c4 = (li & 15) * 4;
            int grow = row0 + r;
            __half2 h0, h1;
            if (grow < N_NODES) {
                if (XKIND == 0) {
                    float4 xv = ((const float4*)Xv)[(size_t)grow * 16 + (li & 15)];
                    h0 = __floats2half2_rn(xv.x, xv.y);
                    h1 = __floats2half2_rn(xv.z, xv.w);
                } else {
                    uint2 pk = ((const uint2*)Xv)[(size_t)grow * 16 + (li & 15)];
                    h0 = *(__half2*)&pk.x;
                    h1 = *(__half2*)&pk.y;
                }
            } else {
                h0 = __floats2half2_rn(0.f, 0.f);
                h1 = h0;
            }
            *(__half2*)&Xs[r][c4]     = h0;
            *(__half2*)&Xs[r][c4 + 2] = h1;
        }
        __syncthreads();   // covers Wh on first tile too

        float d[4][4];
        #pragma unroll
        for (int j = 0; j < 4; j++)
            #pragma unroll
            for (int k = 0; k < 4; k++) d[j][k] = 0.f;

        #pragma unroll
        for (int kk = 0; kk < 4; kk++) {
            uint32_t a0, a1, a2, a3;
            uint32_t addrA = smem_u32(&Xs[rt * 16 + (lane & 15)][kk * 16 + ((lane >> 4) << 3)]);
            asm volatile("ldmatrix.sync.aligned.m8n8.x4.shared.b16 {%0,%1,%2,%3}, [%4];"
                         : "=r"(a0), "=r"(a1), "=r"(a2), "=r"(a3) : "r"(addrA));
            #pragma unroll
            for (int jj = 0; jj < 2; jj++) {
                uint32_t q0, q1, q2, q3;
                uint32_t addrB = smem_u32(&Wh[kk * 16 + (lane & 15)]
                                             [ch * 32 + jj * 16 + ((lane >> 4) << 3)]);
                asm volatile("ldmatrix.sync.aligned.m8n8.x4.trans.shared.b16 {%0,%1,%2,%3}, [%4];"
                             : "=r"(q0), "=r"(q1), "=r"(q2), "=r"(q3) : "r"(addrB));
                int j0 = jj * 2, j1 = jj * 2 + 1;
                asm volatile("mma.sync.aligned.m16n8k16.row.col.f32.f16.f16.f32 "
                             "{%0,%1,%2,%3}, {%4,%5,%6,%7}, {%8,%9}, {%0,%1,%2,%3};"
                             : "+f"(d[j0][0]), "+f"(d[j0][1]), "+f"(d[j0][2]), "+f"(d[j0][3])
                             : "r"(a0), "r"(a1), "r"(a2), "r"(a3), "r"(q0), "r"(q1));
                asm volatile("mma.sync.aligned.m16n8k16.row.col.f32.f16.f16.f32 "
                             "{%0,%1,%2,%3}, {%4,%5,%6,%7}, {%8,%9}, {%0,%1,%2,%3};"
                             : "+f"(d[j1][0]), "+f"(d[j1][1]), "+f"(d[j1][2]), "+f"(d[j1][3])
                             : "r"(a0), "r"(a1), "r"(a2), "r"(a3), "r"(q2), "r"(q3));
            }
        }

        // epilogue: scale by dinv, store fp16 H'
        int r0 = rt * 16 + (lane >> 2);
        int g0 = row0 + r0, g1 = g0 + 8;
        float dv0 = (g0 < N_NODES) ? g_dinv[g0] : 0.f;
        float dv1 = (g1 < N_NODES) ? g_dinv[g1] : 0.f;
        #pragma unroll
        for (int j = 0; j < 4; j++) {
            int c = ch * 32 + j * 8 + (lane & 3) * 2;
            if (g0 < N_NODES)
                *(__half2*)&g_H[(size_t)g0 * 64 + c] = __floats2half2_rn(d[j][0] * dv0, d[j][1] * dv0);
            if (g1 < N_NODES)
                *(__half2*)&g_H[(size_t)g1 * 64 + c] = __floats2half2_rn(d[j][2] * dv1, d[j][3] * dv1);
        }
        __syncthreads();
    }
}

// ---------------- agg phase: out = dinv[i]*(sum H'[u] + H'[i]) + b ------------
// outHalf=1 -> write fp16 (g_Ah); outHalf=0 -> write fp32 (final out).
__device__ __forceinline__ void agg_phase(const float* __restrict__ b,
                                          void* __restrict__ outp,
                                          int relu, int outHalf,
                                          int lane, int wid, int bid) {
    const __half2* H2 = (const __half2*)g_H;
    for (int rg = bid; rg < NRG; rg += NBLK) {
        int row = rg * 8 + wid;
        if (row >= N_NODES) continue;

        int s = g_rowstart[row];
        int e = g_rowstart[row + 1];
        float2 acc = make_float2(0.f, 0.f);

        for (int base = s; base < e; base += 32) {
            int idx = base + lane;
            int uu = (idx < e) ? __ldg(&g_csrsrc[idx]) : N_NODES;   // pad row -> +0
            int cnt = e - base;
            if (cnt > 32) cnt = 32;
            for (int g0 = 0; g0 < cnt; g0 += 8) {
                int u[8];
                #pragma unroll
                for (int j = 0; j < 8; j++)
                    u[j] = __shfl_sync(0xFFFFFFFFu, uu, g0 + j);
                __half2 v[8];
                #pragma unroll
                for (int j = 0; j < 8; j++)
                    v[j] = H2[(size_t)u[j] * 32 + lane];
                #pragma unroll
                for (int j = 0; j < 8; j++) {
                    float2 vf = __half22float2(v[j]);
                    acc.x += vf.x;
                    acc.y += vf.y;
                }
            }
        }

        float dv = g_dinv[row];
        float2 hr = __half22float2(H2[(size_t)row * 32 + lane]);
        float2 bv = ((const float2*)b)[lane];
        acc.x = fmaf(acc.x + hr.x, dv, bv.x);
        acc.y = fmaf(acc.y + hr.y, dv, bv.y);
        if (relu) {
            acc.x = fmaxf(acc.x, 0.f);
            acc.y = fmaxf(acc.y, 0.f);
        }
        if (outHalf)
            *(__half2*)((__half*)outp + (size_t)row * 64 + lane * 2) =
                __floats2half2_rn(acc.x, acc.y);
        else
            ((float2*)((float*)outp + (size_t)row * 64))[lane] = acc;
    }
}

// ---------------- the megakernel ----------------------------------------------
__global__ __launch_bounds__(TPB, 4) void mega_kernel(
    const float* __restrict__ x,
    const int*   __restrict__ src,
    const int*   __restrict__ dst,
    const float* __restrict__ W1, const float* __restrict__ b1,
    const float* __restrict__ W2, const float* __restrict__ b2,
    const float* __restrict__ W3, const float* __restrict__ b3,
    float* __restrict__ out)
{
    __shared__ __half Xs[64][72];
    __shared__ __half Wh[64][72];
    __shared__ int    s_wsum[8];
    __shared__ int    s_prefix;

    int tid = threadIdx.x;
    int bid = blockIdx.x;
    int lane = tid & 31, wid = tid >> 5;

    // ---- phase 0: degree histogram; zero H' pad row ----
    if (bid == 0 && tid < 16)
        ((uint2*)(g_H + (size_t)N_NODES * FEAT))[tid] = make_uint2(0u, 0u);
    for (int e4 = bid * TPB + tid; e4 < NE4; e4 += NBLK * TPB) {
        int4 d = __ldg(&((const int4*)dst)[e4]);
        atomicAdd(&g_zr[d.x], 1);
        atomicAdd(&g_zr[d.y], 1);
        atomicAdd(&g_zr[d.z], 1);
        atomicAdd(&g_zr[d.w], 1);
    }
    grid_barrier();

    // ---- phase 1: lookback scan -> rowstart, cursor, dinv ----
    if (bid < SCAN_NBLOCKS) {
        int idx0 = bid * SCAN_CHUNK + tid * SCAN_PT;
        int v[SCAN_PT];
        int sum = 0;
        #pragma unroll
        for (int j = 0; j < SCAN_PT; j++) {
            int i = idx0 + j;
            v[j] = (i < N_NODES) ? g_zr[i] : 0;
            sum += v[j];
        }
        int xsc = sum;
        #pragma unroll
        for (int d2 = 1; d2 < 32; d2 <<= 1) {
            int t2 = __shfl_up_sync(0xFFFFFFFFu, xsc, d2);
            if (lane >= d2) xsc += t2;
        }
        if (lane == 31) s_wsum[wid] = xsc;
        __syncthreads();
        if (wid == 0) {
            int sv = (lane < 8) ? s_wsum[lane] : 0;
            #pragma unroll
            for (int d2 = 1; d2 < 8; d2 <<= 1) {
                int t2 = __shfl_up_sync(0xFFFFFFFFu, sv, d2);
                if (lane >= d2) sv += t2;
            }
            if (lane < 8) s_wsum[lane] = sv;
        }
        __syncthreads();
        int thr_excl = (xsc - sum) + (wid ? s_wsum[wid - 1] : 0);
        int blk_total = s_wsum[7];

        if (tid == 0) {
            int pre = 0;
            if (bid > 0) {
                int f;
                do { f = atomicAdd(&g_zr[N_NODES + bid - 1], 0); } while (f == 0);
                pre = f & FLAG_MASK;
            }
            __threadfence();
            atomicExch(&g_zr[N_NODES + bid], FLAG_VALID | (pre + blk_total));
            s_prefix = pre;
            if (bid == SCAN_NBLOCKS - 1) g_rowstart[N_NODES] = pre + blk_total;
        }
        __syncthreads();
        int run = s_prefix + thr_excl;
        #pragma unroll
        for (int j = 0; j < SCAN_PT; j++) {
            int i = idx0 + j;
            if (i < N_NODES) {
                g_rowstart[i] = run;
                g_cursor[i]   = run;
                g_dinv[i] = rsqrtf((float)v[j] + 1.0f);
            }
            run += v[j];
        }
    }
    grid_barrier();

    // ---- phase 2: csr build (src only) + gemm1 (tensor cores) ----
    for (int e4 = bid * TPB + tid; e4 < NE4; e4 += NBLK * TPB) {
        int4 s4 = __ldg(&((const int4*)src)[e4]);
        int4 d4 = __ldg(&((const int4*)dst)[e4]);
        g_csrsrc[atomicAdd(&g_cursor[d4.x], 1)] = s4.x;
        g_csrsrc[atomicAdd(&g_cursor[d4.y], 1)] = s4.y;
        g_csrsrc[atomicAdd(&g_cursor[d4.z], 1)] = s4.z;
        g_csrsrc[atomicAdd(&g_cursor[d4.w], 1)] = s4.w;
    }
    gemm_phase_mma<0>(x, W1, tid, bid, Xs, Wh);
    grid_barrier();

    // ---- layers ----
    agg_phase(b1, g_Ah, 1, 1, lane, wid, bid);
    grid_barrier();
    gemm_phase_mma<1>(g_Ah, W2, tid, bid, Xs, Wh);
    grid_barrier();
    agg_phase(b2, g_Ah, 1, 1, lane, wid, bid);
    grid_barrier();
    gemm_phase_mma<1>(g_Ah, W3, tid, bid, Xs, Wh);
    grid_barrier();
    agg_phase(b3, out, 0, 0, lane, wid, bid);
}

// ---------------- launch ------------------------------------------------------

extern "C" void kernel_launch(void* const* d_in, const int* in_sizes, int n_in,
                              void* d_out, int out_size) {
    const float* x   = (const float*)d_in[0];
    const int*   ei  = (const int*)d_in[1];
    const float* W1  = (const float*)d_in[2];
    const float* b1  = (const float*)d_in[3];
    const float* W2  = (const float*)d_in[4];
    const float* b2  = (const float*)d_in[5];
    const float* W3  = (const float*)d_in[6];
    const float* b3  = (const float*)d_in[7];
    float* out = (float*)d_out;

    const int* src = ei;
    const int* dst = ei + N_EDGES;

    void* zr_ptr = nullptr;
    cudaGetSymbolAddress(&zr_ptr, g_zr);
    cudaMemsetAsync(zr_ptr, 0, sizeof(int) * (N_NODES + 64));

    mega_kernel<<<NBLK, TPB>>>(x, src, dst, W1, b1, W2, b2, W3, b3, out);

    (void)in_sizes; (void)n_in; (void)out_size;
}

// round 14
// speedup vs baseline: 3.0969x; 1.0102x over previous
#include <cuda_runtime.h>
#include <cuda_fp16.h>
#include <cstdint>

#define N_NODES 100000
#define N_EDGES 1600000
#define FEAT 64
#define TPB 256
#define NBLK 592                              // 148 SMs x 4 blocks, co-resident
#define NTILE ((N_NODES + 63) / 64)           // 1563 gemm tiles
#define NE4 (N_EDGES / 4)                     // 400000
#define NRG ((N_NODES + 7) / 8)               // 12500 row groups
#define NH2 (N_NODES * 32)                    // half2 words in H

#define SCAN_PT 16
#define SCAN_CHUNK (TPB * SCAN_PT)            // 4096
#define SCAN_NBLOCKS ((N_NODES + SCAN_CHUNK - 1) / SCAN_CHUNK)   // 25
#define FLAG_VALID (1 << 30)
#define FLAG_MASK  (FLAG_VALID - 1)

// ---------------- scratch (static device globals: allocation-free) ----------
// H' = dinv * (X@W), fp16, ONE zero pad row at index N_NODES.
__device__ __half g_H[(N_NODES + 1) * FEAT];
__device__ __half g_Ah[N_NODES * FEAT];       // activations, fp16 storage
__device__ float  g_dinv[N_NODES];
__device__ int    g_rowstart[N_NODES + 1];
__device__ int    g_cursor[N_NODES];
__device__ int    g_csrsrc[N_EDGES];          // src-only CSR (norm folded into H')
__device__ int    g_zr[N_NODES + 64];         // deg + lookback flags (one memset)
__device__ unsigned g_barTicket = 0;          // monotone grid barrier (replay-safe)

__device__ __forceinline__ uint32_t smem_u32(const void* p) {
    return (uint32_t)__cvta_generic_to_shared(p);
}

// ---- grid-wide barrier ----
__device__ __forceinline__ void grid_barrier() {
    __syncthreads();
    if (threadIdx.x == 0) {
        __threadfence();
        unsigned old = atomicAdd(&g_barTicket, 1u);
        unsigned target = (old / NBLK + 1u) * NBLK;
        while (atomicAdd(&g_barTicket, 0u) < target) __nanosleep(64);
        __threadfence();
    }
    __syncthreads();
}

// ---------------- tensor-core gemm ---------------------------------------------
// 64x64 tile / block; 8 warps; warp = 16 rows x 32 cols via mma.m16n8k16.
// XKIND 0: X fp32 global. XKIND 1: X fp16 global. DINV: scale epilogue by g_dinv.
template<int XKIND, int DINV>
__device__ __forceinline__ void gemm_phase_mma(const void* Xv,
                                               const float* __restrict__ W,
                                               int tid, int bid,
                                               __half (*Xs)[72], __half (*Wh)[72]) {
    {
        const float4* W4 = (const float4*)W;
        #pragma unroll
        for (int i = 0; i < 4; i++) {
            int li = tid + 256 * i;
            int r = li >> 4, c4 = (li & 15) * 4;
            float4 w = W4[li];
            *(__half2*)&Wh[r][c4]     = __floats2half2_rn(w.x, w.y);
            *(__half2*)&Wh[r][c4 + 2] = __floats2half2_rn(w.z, w.w);
        }
    }
    int lane = tid & 31, w8 = tid >> 5;
    int rt = w8 & 3;
    int ch = w8 >> 2;

    for (int t = bid; t < NTILE; t += NBLK) {
        int row0 = t * 64;
        #pragma unroll
        for (int i = 0; i < 4; i++) {
            int li = tid + 256 * i;
            int r = li >> 4, c4 = (li & 15) * 4;
            int grow = row0 + r;
            __half2 h0, h1;
            if (grow < N_NODES) {
                if (XKIND == 0) {
                    float4 xv = ((const float4*)Xv)[(size_t)grow * 16 + (li & 15)];
                    h0 = __floats2half2_rn(xv.x, xv.y);
                    h1 = __floats2half2_rn(xv.z, xv.w);
                } else {
                    uint2 pk = ((const uint2*)Xv)[(size_t)grow * 16 + (li & 15)];
                    h0 = *(__half2*)&pk.x;
                    h1 = *(__half2*)&pk.y;
                }
            } else {
                h0 = __floats2half2_rn(0.f, 0.f);
                h1 = h0;
            }
            *(__half2*)&Xs[r][c4]     = h0;
            *(__half2*)&Xs[r][c4 + 2] = h1;
        }
        __syncthreads();

        float d[4][4];
        #pragma unroll
        for (int j = 0; j < 4; j++)
            #pragma unroll
            for (int k = 0; k < 4; k++) d[j][k] = 0.f;

        #pragma unroll
        for (int kk = 0; kk < 4; kk++) {
            uint32_t a0, a1, a2, a3;
            uint32_t addrA = smem_u32(&Xs[rt * 16 + (lane & 15)][kk * 16 + ((lane >> 4) << 3)]);
            asm volatile("ldmatrix.sync.aligned.m8n8.x4.shared.b16 {%0,%1,%2,%3}, [%4];"
                         : "=r"(a0), "=r"(a1), "=r"(a2), "=r"(a3) : "r"(addrA));
            #pragma unroll
            for (int jj = 0; jj < 2; jj++) {
                uint32_t q0, q1, q2, q3;
                uint32_t addrB = smem_u32(&Wh[kk * 16 + (lane & 15)]
                                             [ch * 32 + jj * 16 + ((lane >> 4) << 3)]);
                asm volatile("ldmatrix.sync.aligned.m8n8.x4.trans.shared.b16 {%0,%1,%2,%3}, [%4];"
                             : "=r"(q0), "=r"(q1), "=r"(q2), "=r"(q3) : "r"(addrB));
                int j0 = jj * 2, j1 = jj * 2 + 1;
                asm volatile("mma.sync.aligned.m16n8k16.row.col.f32.f16.f16.f32 "
                             "{%0,%1,%2,%3}, {%4,%5,%6,%7}, {%8,%9}, {%0,%1,%2,%3};"
                             : "+f"(d[j0][0]), "+f"(d[j0][1]), "+f"(d[j0][2]), "+f"(d[j0][3])
                             : "r"(a0), "r"(a1), "r"(a2), "r"(a3), "r"(q0), "r"(q1));
                asm volatile("mma.sync.aligned.m16n8k16.row.col.f32.f16.f16.f32 "
                             "{%0,%1,%2,%3}, {%4,%5,%6,%7}, {%8,%9}, {%0,%1,%2,%3};"
                             : "+f"(d[j1][0]), "+f"(d[j1][1]), "+f"(d[j1][2]), "+f"(d[j1][3])
                             : "r"(a0), "r"(a1), "r"(a2), "r"(a3), "r"(q2), "r"(q3));
            }
        }

        int r0 = rt * 16 + (lane >> 2);
        int g0 = row0 + r0, g1 = g0 + 8;
        float dv0 = 1.f, dv1 = 1.f;
        if (DINV) {
            dv0 = (g0 < N_NODES) ? g_dinv[g0] : 0.f;
            dv1 = (g1 < N_NODES) ? g_dinv[g1] : 0.f;
        }
        #pragma unroll
        for (int j = 0; j < 4; j++) {
            int c = ch * 32 + j * 8 + (lane & 3) * 2;
            if (g0 < N_NODES)
                *(__half2*)&g_H[(size_t)g0 * 64 + c] = __floats2half2_rn(d[j][0] * dv0, d[j][1] * dv0);
            if (g1 < N_NODES)
                *(__half2*)&g_H[(size_t)g1 * 64 + c] = __floats2half2_rn(d[j][2] * dv1, d[j][3] * dv1);
        }
        __syncthreads();
    }
}

// ---------------- agg phase: out = dinv[i]*(sum H'[u] + H'[i]) + b ------------
__device__ __forceinline__ void agg_phase(const float* __restrict__ b,
                                          void* __restrict__ outp,
                                          int relu, int outHalf,
                                          int lane, int wid, int bid) {
    const __half2* H2 = (const __half2*)g_H;
    for (int rg = bid; rg < NRG; rg += NBLK) {
        int row = rg * 8 + wid;
        if (row >= N_NODES) continue;

        int s = g_rowstart[row];
        int e = g_rowstart[row + 1];
        float2 acc = make_float2(0.f, 0.f);

        for (int base = s; base < e; base += 32) {
            int idx = base + lane;
            int uu = (idx < e) ? __ldg(&g_csrsrc[idx]) : N_NODES;   // pad row -> +0
            int cnt = e - base;
            if (cnt > 32) cnt = 32;
            for (int g0 = 0; g0 < cnt; g0 += 8) {
                int u[8];
                #pragma unroll
                for (int j = 0; j < 8; j++)
                    u[j] = __shfl_sync(0xFFFFFFFFu, uu, g0 + j);
                __half2 v[8];
                #pragma unroll
                for (int j = 0; j < 8; j++)
                    v[j] = H2[(size_t)u[j] * 32 + lane];
                // pairwise half add (1 rounding per pair), then fp32 accumulate
                #pragma unroll
                for (int j = 0; j < 8; j += 2) {
                    float2 vf = __half22float2(__hadd2(v[j], v[j + 1]));
                    acc.x += vf.x;
                    acc.y += vf.y;
                }
            }
        }

        float dv = g_dinv[row];
        float2 hr = __half22float2(H2[(size_t)row * 32 + lane]);
        float2 bv = ((const float2*)b)[lane];
        acc.x = fmaf(acc.x + hr.x, dv, bv.x);
        acc.y = fmaf(acc.y + hr.y, dv, bv.y);
        if (relu) {
            acc.x = fmaxf(acc.x, 0.f);
            acc.y = fmaxf(acc.y, 0.f);
        }
        if (outHalf)
            *(__half2*)((__half*)outp + (size_t)row * 64 + lane * 2) =
                __floats2half2_rn(acc.x, acc.y);
        else
            ((float2*)((float*)outp + (size_t)row * 64))[lane] = acc;
    }
}

// ---------------- the megakernel ----------------------------------------------
__global__ __launch_bounds__(TPB, 4) void mega_kernel(
    const float* __restrict__ x,
    const int*   __restrict__ src,
    const int*   __restrict__ dst,
    const float* __restrict__ W1, const float* __restrict__ b1,
    const float* __restrict__ W2, const float* __restrict__ b2,
    const float* __restrict__ W3, const float* __restrict__ b3,
    float* __restrict__ out)
{
    __shared__ __half Xs[64][72];
    __shared__ __half Wh[64][72];
    __shared__ int    s_wsum[8];
    __shared__ int    s_prefix;

    int tid = threadIdx.x;
    int bid = blockIdx.x;
    int lane = tid & 31, wid = tid >> 5;

    // ---- phase 0: degree histogram + RAW gemm1 (T = X@W1, no dinv yet) ----
    if (bid == 0 && tid < 16)
        ((uint2*)(g_H + (size_t)N_NODES * FEAT))[tid] = make_uint2(0u, 0u);
    for (int e4 = bid * TPB + tid; e4 < NE4; e4 += NBLK * TPB) {
        int4 d = __ldg(&((const int4*)dst)[e4]);
        atomicAdd(&g_zr[d.x], 1);
        atomicAdd(&g_zr[d.y], 1);
        atomicAdd(&g_zr[d.z], 1);
        atomicAdd(&g_zr[d.w], 1);
    }
    gemm_phase_mma<0, 0>(x, W1, tid, bid, Xs, Wh);
    grid_barrier();

    // ---- phase 1: lookback scan -> rowstart, cursor, dinv ----
    if (bid < SCAN_NBLOCKS) {
        int idx0 = bid * SCAN_CHUNK + tid * SCAN_PT;
        int v[SCAN_PT];
        int sum = 0;
        #pragma unroll
        for (int j = 0; j < SCAN_PT; j++) {
            int i = idx0 + j;
            v[j] = (i < N_NODES) ? g_zr[i] : 0;
            sum += v[j];
        }
        int xsc = sum;
        #pragma unroll
        for (int d2 = 1; d2 < 32; d2 <<= 1) {
            int t2 = __shfl_up_sync(0xFFFFFFFFu, xsc, d2);
            if (lane >= d2) xsc += t2;
        }
        if (lane == 31) s_wsum[wid] = xsc;
        __syncthreads();
        if (wid == 0) {
            int sv = (lane < 8) ? s_wsum[lane] : 0;
            #pragma unroll
            for (int d2 = 1; d2 < 8; d2 <<= 1) {
                int t2 = __shfl_up_sync(0xFFFFFFFFu, sv, d2);
                if (lane >= d2) sv += t2;
            }
            if (lane < 8) s_wsum[lane] = sv;
        }
        __syncthreads();
        int thr_excl = (xsc - sum) + (wid ? s_wsum[wid - 1] : 0);
        int blk_total = s_wsum[7];

        if (tid == 0) {
            int pre = 0;
            if (bid > 0) {
                int f;
                do { f = atomicAdd(&g_zr[N_NODES + bid - 1], 0); } while (f == 0);
                pre = f & FLAG_MASK;
            }
            __threadfence();
            atomicExch(&g_zr[N_NODES + bid], FLAG_VALID | (pre + blk_total));
            s_prefix = pre;
            if (bid == SCAN_NBLOCKS - 1) g_rowstart[N_NODES] = pre + blk_total;
        }
        __syncthreads();
        int run = s_prefix + thr_excl;
        #pragma unroll
        for (int j = 0; j < SCAN_PT; j++) {
            int i = idx0 + j;
            if (i < N_NODES) {
                g_rowstart[i] = run;
                g_cursor[i]   = run;
                g_dinv[i] = rsqrtf((float)v[j] + 1.0f);
            }
            run += v[j];
        }
    }
    grid_barrier();

    // ---- phase 2: csr build + in-place H scale (H = dinv .* T), overlapped ----
    for (int e4 = bid * TPB + tid; e4 < NE4; e4 += NBLK * TPB) {
        int4 s4 = __ldg(&((const int4*)src)[e4]);
        int4 d4 = __ldg(&((const int4*)dst)[e4]);
        g_csrsrc[atomicAdd(&g_cursor[d4.x], 1)] = s4.x;
        g_csrsrc[atomicAdd(&g_cursor[d4.y], 1)] = s4.y;
        g_csrsrc[atomicAdd(&g_cursor[d4.z], 1)] = s4.z;
        g_csrsrc[atomicAdd(&g_cursor[d4.w], 1)] = s4.w;
    }
    {
        __half2* H2 = (__half2*)g_H;
        for (int i = bid * TPB + tid; i < NH2; i += NBLK * TPB) {
            int row = i >> 5;
            float dv = g_dinv[row];
            float2 vf = __half22float2(H2[i]);
            H2[i] = __floats2half2_rn(vf.x * dv, vf.y * dv);
        }
    }
    grid_barrier();

    // ---- layers ----
    agg_phase(b1, g_Ah, 1, 1, lane, wid, bid);
    grid_barrier();
    gemm_phase_mma<1, 1>(g_Ah, W2, tid, bid, Xs, Wh);
    grid_barrier();
    agg_phase(b2, g_Ah, 1, 1, lane, wid, bid);
    grid_barrier();
    gemm_phase_mma<1, 1>(g_Ah, W3, tid, bid, Xs, Wh);
    grid_barrier();
    agg_phase(b3, out, 0, 0, lane, wid, bid);
}

// ---------------- launch ------------------------------------------------------

extern "C" void kernel_launch(void* const* d_in, const int* in_sizes, int n_in,
                              void* d_out, int out_size) {
    const float* x   = (const float*)d_in[0];
    const int*   ei  = (const int*)d_in[1];
    const float* W1  = (const float*)d_in[2];
    const float* b1  = (const float*)d_in[3];
    const float* W2  = (const float*)d_in[4];
    const float* b2  = (const float*)d_in[5];
    const float* W3  = (const float*)d_in[6];
    const float* b3  = (const float*)d_in[7];
    float* out = (float*)d_out;

    const int* src = ei;
    const int* dst = ei + N_EDGES;

    void* zr_ptr = nullptr;
    cudaGetSymbolAddress(&zr_ptr, g_zr);
    cudaMemsetAsync(zr_ptr, 0, sizeof(int) * (N_NODES + 64));

    mega_kernel<<<NBLK, TPB>>>(x, src, dst, W1, b1, W2, b2, W3, b3, out);

    (void)in_sizes; (void)n_in; (void)out_size;
}

// round 15
// speedup vs baseline: 3.2903x; 1.0624x over previous
#include <cuda_runtime.h>
#include <cuda_fp16.h>
#include <cstdint>

#define N_NODES 100000
#define N_EDGES 1600000
#define FEAT 64
#define TPB 256
#define NBLK 592                              // 148 SMs x 4 blocks, co-resident
#define NTILE ((N_NODES + 63) / 64)           // 1563 gemm tiles
#define NE4 (N_EDGES / 4)                     // 400000
#define NRG2 (N_NODES / 16)                   // 6250 row-pair groups (16 rows/block)
#define NH2 (N_NODES * 32)                    // half2 words in H

#define SCAN_PT 16
#define SCAN_CHUNK (TPB * SCAN_PT)            // 4096
#define SCAN_NBLOCKS ((N_NODES + SCAN_CHUNK - 1) / SCAN_CHUNK)   // 25
#define FLAG_VALID (1 << 30)
#define FLAG_MASK  (FLAG_VALID - 1)

// ---------------- scratch (static device globals: allocation-free) ----------
// H' = dinv * (X@W), fp16, ONE zero pad row at index N_NODES.
__device__ __half g_H[(N_NODES + 1) * FEAT];
__device__ __half g_Ah[N_NODES * FEAT];       // activations, fp16 storage
__device__ float  g_dinv[N_NODES];
__device__ int    g_rowstart[N_NODES + 1];
__device__ int    g_cursor[N_NODES];
__device__ int    g_csrsrc[N_EDGES];          // src-only CSR (norm folded into H')
__device__ int    g_zr[N_NODES + 64];         // deg + lookback flags (one memset)
__device__ unsigned g_barTicket = 0;          // monotone grid barrier (replay-safe)

__device__ __forceinline__ uint32_t smem_u32(const void* p) {
    return (uint32_t)__cvta_generic_to_shared(p);
}

// ---- grid-wide barrier ----
__device__ __forceinline__ void grid_barrier() {
    __syncthreads();
    if (threadIdx.x == 0) {
        __threadfence();
        unsigned old = atomicAdd(&g_barTicket, 1u);
        unsigned target = (old / NBLK + 1u) * NBLK;
        while (atomicAdd(&g_barTicket, 0u) < target) __nanosleep(64);
        __threadfence();
    }
    __syncthreads();
}

// ---------------- tensor-core gemm ---------------------------------------------
template<int XKIND, int DINV>
__device__ __forceinline__ void gemm_phase_mma(const void* Xv,
                                               const float* __restrict__ W,
                                               int tid, int bid,
                                               __half (*Xs)[72], __half (*Wh)[72]) {
    {
        const float4* W4 = (const float4*)W;
        #pragma unroll
        for (int i = 0; i < 4; i++) {
            int li = tid + 256 * i;
            int r = li >> 4, c4 = (li & 15) * 4;
            float4 w = W4[li];
            *(__half2*)&Wh[r][c4]     = __floats2half2_rn(w.x, w.y);
            *(__half2*)&Wh[r][c4 + 2] = __floats2half2_rn(w.z, w.w);
        }
    }
    int lane = tid & 31, w8 = tid >> 5;
    int rt = w8 & 3;
    int ch = w8 >> 2;

    for (int t = bid; t < NTILE; t += NBLK) {
        int row0 = t * 64;
        #pragma unroll
        for (int i = 0; i < 4; i++) {
            int li = tid + 256 * i;
            int r = li >> 4, c4 = (li & 15) * 4;
            int grow = row0 + r;
            __half2 h0, h1;
            if (grow < N_NODES) {
                if (XKIND == 0) {
                    float4 xv = ((const float4*)Xv)[(size_t)grow * 16 + (li & 15)];
                    h0 = __floats2half2_rn(xv.x, xv.y);
                    h1 = __floats2half2_rn(xv.z, xv.w);
                } else {
                    uint2 pk = ((const uint2*)Xv)[(size_t)grow * 16 + (li & 15)];
                    h0 = *(__half2*)&pk.x;
                    h1 = *(__half2*)&pk.y;
                }
            } else {
                h0 = __floats2half2_rn(0.f, 0.f);
                h1 = h0;
            }
            *(__half2*)&Xs[r][c4]     = h0;
            *(__half2*)&Xs[r][c4 + 2] = h1;
        }
        __syncthreads();

        float d[4][4];
        #pragma unroll
        for (int j = 0; j < 4; j++)
            #pragma unroll
            for (int k = 0; k < 4; k++) d[j][k] = 0.f;

        #pragma unroll
        for (int kk = 0; kk < 4; kk++) {
            uint32_t a0, a1, a2, a3;
            uint32_t addrA = smem_u32(&Xs[rt * 16 + (lane & 15)][kk * 16 + ((lane >> 4) << 3)]);
            asm volatile("ldmatrix.sync.aligned.m8n8.x4.shared.b16 {%0,%1,%2,%3}, [%4];"
                         : "=r"(a0), "=r"(a1), "=r"(a2), "=r"(a3) : "r"(addrA));
            #pragma unroll
            for (int jj = 0; jj < 2; jj++) {
                uint32_t q0, q1, q2, q3;
                uint32_t addrB = smem_u32(&Wh[kk * 16 + (lane & 15)]
                                             [ch * 32 + jj * 16 + ((lane >> 4) << 3)]);
                asm volatile("ldmatrix.sync.aligned.m8n8.x4.trans.shared.b16 {%0,%1,%2,%3}, [%4];"
                             : "=r"(q0), "=r"(q1), "=r"(q2), "=r"(q3) : "r"(addrB));
                int j0 = jj * 2, j1 = jj * 2 + 1;
                asm volatile("mma.sync.aligned.m16n8k16.row.col.f32.f16.f16.f32 "
                             "{%0,%1,%2,%3}, {%4,%5,%6,%7}, {%8,%9}, {%0,%1,%2,%3};"
                             : "+f"(d[j0][0]), "+f"(d[j0][1]), "+f"(d[j0][2]), "+f"(d[j0][3])
                             : "r"(a0), "r"(a1), "r"(a2), "r"(a3), "r"(q0), "r"(q1));
                asm volatile("mma.sync.aligned.m16n8k16.row.col.f32.f16.f16.f32 "
                             "{%0,%1,%2,%3}, {%4,%5,%6,%7}, {%8,%9}, {%0,%1,%2,%3};"
                             : "+f"(d[j1][0]), "+f"(d[j1][1]), "+f"(d[j1][2]), "+f"(d[j1][3])
                             : "r"(a0), "r"(a1), "r"(a2), "r"(a3), "r"(q2), "r"(q3));
            }
        }

        int r0 = rt * 16 + (lane >> 2);
        int g0 = row0 + r0, g1 = g0 + 8;
        float dv0 = 1.f, dv1 = 1.f;
        if (DINV) {
            dv0 = (g0 < N_NODES) ? g_dinv[g0] : 0.f;
            dv1 = (g1 < N_NODES) ? g_dinv[g1] : 0.f;
        }
        #pragma unroll
        for (int j = 0; j < 4; j++) {
            int c = ch * 32 + j * 8 + (lane & 3) * 2;
            if (g0 < N_NODES)
                *(__half2*)&g_H[(size_t)g0 * 64 + c] = __floats2half2_rn(d[j][0] * dv0, d[j][1] * dv0);
            if (g1 < N_NODES)
                *(__half2*)&g_H[(size_t)g1 * 64 + c] = __floats2half2_rn(d[j][2] * dv1, d[j][3] * dv1);
        }
        __syncthreads();
    }
}

// ---------------- agg phase: TWO rows per warp (doubles per-warp MLP) ----------
// out[i] = dinv[i]*(sum_u H'[u] + H'[i]) + b ; pad gathers hit zero row (L1-hot).
__device__ __forceinline__ void agg_phase(const float* __restrict__ b,
                                          void* __restrict__ outp,
                                          int relu, int outHalf,
                                          int lane, int wid, int bid) {
    const __half2* H2 = (const __half2*)g_H;
    for (int rg = bid; rg < NRG2; rg += NBLK) {
        int rowA = rg * 16 + wid * 2;          // N_NODES = 16*NRG2, always in range
        int rowB = rowA + 1;

        int sA = g_rowstart[rowA];
        int eA = g_rowstart[rowA + 1];
        int sB = eA;                           // rows adjacent: sB = rowstart[rowB]
        int eB = g_rowstart[rowB + 1];
        int dmax = max(eA - sA, eB - sB);

        float2 accA = make_float2(0.f, 0.f);
        float2 accB = make_float2(0.f, 0.f);

        for (int off = 0; off < dmax; off += 32) {
            int iA = sA + off + lane;
            int iB = sB + off + lane;
            int uuA = (iA < eA) ? __ldg(&g_csrsrc[iA]) : N_NODES;
            int uuB = (iB < eB) ? __ldg(&g_csrsrc[iB]) : N_NODES;
            int cnt = dmax - off;
            if (cnt > 32) cnt = 32;
            for (int g0 = 0; g0 < cnt; g0 += 8) {
                int uA[8], uB[8];
                #pragma unroll
                for (int j = 0; j < 8; j++) {
                    uA[j] = __shfl_sync(0xFFFFFFFFu, uuA, g0 + j);
                    uB[j] = __shfl_sync(0xFFFFFFFFu, uuB, g0 + j);
                }
                __half2 vA[8], vB[8];
                #pragma unroll
                for (int j = 0; j < 8; j++)
                    vA[j] = H2[(size_t)uA[j] * 32 + lane];
                #pragma unroll
                for (int j = 0; j < 8; j++)
                    vB[j] = H2[(size_t)uB[j] * 32 + lane];
                #pragma unroll
                for (int j = 0; j < 8; j += 2) {
                    float2 fa = __half22float2(__hadd2(vA[j], vA[j + 1]));
                    float2 fb = __half22float2(__hadd2(vB[j], vB[j + 1]));
                    accA.x += fa.x;  accA.y += fa.y;
                    accB.x += fb.x;  accB.y += fb.y;
                }
            }
        }

        float dvA = g_dinv[rowA];
        float dvB = g_dinv[rowB];
        float2 hA = __half22float2(H2[(size_t)rowA * 32 + lane]);
        float2 hB = __half22float2(H2[(size_t)rowB * 32 + lane]);
        float2 bv = ((const float2*)b)[lane];
        accA.x = fmaf(accA.x + hA.x, dvA, bv.x);
        accA.y = fmaf(accA.y + hA.y, dvA, bv.y);
        accB.x = fmaf(accB.x + hB.x, dvB, bv.x);
        accB.y = fmaf(accB.y + hB.y, dvB, bv.y);
        if (relu) {
            accA.x = fmaxf(accA.x, 0.f);  accA.y = fmaxf(accA.y, 0.f);
            accB.x = fmaxf(accB.x, 0.f);  accB.y = fmaxf(accB.y, 0.f);
        }
        if (outHalf) {
            *(__half2*)((__half*)outp + (size_t)rowA * 64 + lane * 2) =
                __floats2half2_rn(accA.x, accA.y);
            *(__half2*)((__half*)outp + (size_t)rowB * 64 + lane * 2) =
                __floats2half2_rn(accB.x, accB.y);
        } else {
            ((float2*)((float*)outp + (size_t)rowA * 64))[lane] = accA;
            ((float2*)((float*)outp + (size_t)rowB * 64))[lane] = accB;
        }
    }
}

// ---------------- the megakernel ----------------------------------------------
__global__ __launch_bounds__(TPB, 4) void mega_kernel(
    const float* __restrict__ x,
    const int*   __restrict__ src,
    const int*   __restrict__ dst,
    const float* __restrict__ W1, const float* __restrict__ b1,
    const float* __restrict__ W2, const float* __restrict__ b2,
    const float* __restrict__ W3, const float* __restrict__ b3,
    float* __restrict__ out)
{
    __shared__ __half Xs[64][72];
    __shared__ __half Wh[64][72];
    __shared__ int    s_wsum[8];
    __shared__ int    s_prefix;

    int tid = threadIdx.x;
    int bid = blockIdx.x;
    int lane = tid & 31, wid = tid >> 5;

    // ---- phase 0: degree histogram + RAW gemm1 (T = X@W1, no dinv yet) ----
    if (bid == 0 && tid < 16)
        ((uint2*)(g_H + (size_t)N_NODES * FEAT))[tid] = make_uint2(0u, 0u);
    for (int e4 = bid * TPB + tid; e4 < NE4; e4 += NBLK * TPB) {
        int4 d = __ldg(&((const int4*)dst)[e4]);
        atomicAdd(&g_zr[d.x], 1);
        atomicAdd(&g_zr[d.y], 1);
        atomicAdd(&g_zr[d.z], 1);
        atomicAdd(&g_zr[d.w], 1);
    }
    gemm_phase_mma<0, 0>(x, W1, tid, bid, Xs, Wh);
    grid_barrier();

    // ---- phase 1: lookback scan -> rowstart, cursor, dinv ----
    if (bid < SCAN_NBLOCKS) {
        int idx0 = bid * SCAN_CHUNK + tid * SCAN_PT;
        int v[SCAN_PT];
        int sum = 0;
        #pragma unroll
        for (int j = 0; j < SCAN_PT; j++) {
            int i = idx0 + j;
            v[j] = (i < N_NODES) ? g_zr[i] : 0;
            sum += v[j];
        }
        int xsc = sum;
        #pragma unroll
        for (int d2 = 1; d2 < 32; d2 <<= 1) {
            int t2 = __shfl_up_sync(0xFFFFFFFFu, xsc, d2);
            if (lane >= d2) xsc += t2;
        }
        if (lane == 31) s_wsum[wid] = xsc;
        __syncthreads();
        if (wid == 0) {
            int sv = (lane < 8) ? s_wsum[lane] : 0;
            #pragma unroll
            for (int d2 = 1; d2 < 8; d2 <<= 1) {
                int t2 = __shfl_up_sync(0xFFFFFFFFu, sv, d2);
                if (lane >= d2) sv += t2;
            }
            if (lane < 8) s_wsum[lane] = sv;
        }
        __syncthreads();
        int thr_excl = (xsc - sum) + (wid ? s_wsum[wid - 1] : 0);
        int blk_total = s_wsum[7];

        if (tid == 0) {
            int pre = 0;
            if (bid > 0) {
                int f;
                do { f = atomicAdd(&g_zr[N_NODES + bid - 1], 0); } while (f == 0);
                pre = f & FLAG_MASK;
            }
            __threadfence();
            atomicExch(&g_zr[N_NODES + bid], FLAG_VALID | (pre + blk_total));
            s_prefix = pre;
            if (bid == SCAN_NBLOCKS - 1) g_rowstart[N_NODES] = pre + blk_total;
        }
        __syncthreads();
        int run = s_prefix + thr_excl;
        #pragma unroll
        for (int j = 0; j < SCAN_PT; j++) {
            int i = idx0 + j;
            if (i < N_NODES) {
                g_rowstart[i] = run;
                g_cursor[i]   = run;
                g_dinv[i] = rsqrtf((float)v[j] + 1.0f);
            }
            run += v[j];
        }
    }
    grid_barrier();

    // ---- phase 2: csr build + in-place H scale (H = dinv .* T), overlapped ----
    for (int e4 = bid * TPB + tid; e4 < NE4; e4 += NBLK * TPB) {
        int4 s4 = __ldg(&((const int4*)src)[e4]);
        int4 d4 = __ldg(&((const int4*)dst)[e4]);
        g_csrsrc[atomicAdd(&g_cursor[d4.x], 1)] = s4.x;
        g_csrsrc[atomicAdd(&g_cursor[d4.y], 1)] = s4.y;
        g_csrsrc[atomicAdd(&g_cursor[d4.z], 1)] = s4.z;
        g_csrsrc[atomicAdd(&g_cursor[d4.w], 1)] = s4.w;
    }
    {
        __half2* H2 = (__half2*)g_H;
        for (int i = bid * TPB + tid; i < NH2; i += NBLK * TPB) {
            int row = i >> 5;
            float dv = g_dinv[row];
            float2 vf = __half22float2(H2[i]);
            H2[i] = __floats2half2_rn(vf.x * dv, vf.y * dv);
        }
    }
    grid_barrier();

    // ---- layers ----
    agg_phase(b1, g_Ah, 1, 1, lane, wid, bid);
    grid_barrier();
    gemm_phase_mma<1, 1>(g_Ah, W2, tid, bid, Xs, Wh);
    grid_barrier();
    agg_phase(b2, g_Ah, 1, 1, lane, wid, bid);
    grid_barrier();
    gemm_phase_mma<1, 1>(g_Ah, W3, tid, bid, Xs, Wh);
    grid_barrier();
    agg_phase(b3, out, 0, 0, lane, wid, bid);
}

// ---------------- launch ------------------------------------------------------

extern "C" void kernel_launch(void* const* d_in, const int* in_sizes, int n_in,
                              void* d_out, int out_size) {
    const float* x   = (const float*)d_in[0];
    const int*   ei  = (const int*)d_in[1];
    const float* W1  = (const float*)d_in[2];
    const float* b1  = (const float*)d_in[3];
    const float* W2  = (const float*)d_in[4];
    const float* b2  = (const float*)d_in[5];
    const float* W3  = (const float*)d_in[6];
    const float* b3  = (const float*)d_in[7];
    float* out = (float*)d_out;

    const int* src = ei;
    const int* dst = ei + N_EDGES;

    void* zr_ptr = nullptr;
    cudaGetSymbolAddress(&zr_ptr, g_zr);
    cudaMemsetAsync(zr_ptr, 0, sizeof(int) * (N_NODES + 64));

    mega_kernel<<<NBLK, TPB>>>(x, src, dst, W1, b1, W2, b2, W3, b3, out);

    (void)in_sizes; (void)n_in; (void)out_size;
}